// round 4
// baseline (speedup 1.0000x reference)
#include <cuda_runtime.h>
#include <stdint.h>

#define BATCH   16
#define NANCH   25200
#define NCLS    80
#define ROWLEN  85
#define KCAP    4096
#define MAXDET  300
#define CONF    0.45f
#define IOUT    0.45f
#define MAXWH   4096.0f
#define CLSCAP  256

// -------- device scratch --------
__device__ int                g_count[BATCH];
__device__ unsigned long long g_keys[BATCH][KCAP];

// -------- kernel 1: warp-cooperative confidence filter --------
__global__ void __launch_bounds__(256) filter_kernel(const float* __restrict__ pred) {
    int t    = blockIdx.x * blockDim.x + threadIdx.x;
    int lane = threadIdx.x & 31;
    bool valid = t < BATCH * NANCH;
    int img = valid ? t / NANCH : 0;
    int a   = valid ? t - img * NANCH : 0;
    float obj = valid ? pred[(long long)t * ROWLEN + 4] : 0.f;

    unsigned pa = __ballot_sync(0xffffffffu, obj > CONF);
    while (pa) {
        int src = __ffs(pa) - 1;
        pa &= pa - 1;
        int   simg = __shfl_sync(0xffffffffu, img, src);
        int   sa   = __shfl_sync(0xffffffffu, a,   src);
        float sobj = __shfl_sync(0xffffffffu, obj, src);
        const float* row = pred + ((long long)simg * NANCH + sa) * ROWLEN;

        int c0 = lane, c1 = lane + 32, c2 = lane + 64;
        float s0 = __fmul_rn(row[5 + c0], sobj);
        float s1 = __fmul_rn(row[5 + c1], sobj);
        float s2 = (c2 < NCLS) ? __fmul_rn(row[5 + c2], sobj) : 0.f;
        bool p0 = s0 > CONF, p1 = s1 > CONF, p2 = (c2 < NCLS) && (s2 > CONF);
        unsigned b0 = __ballot_sync(0xffffffffu, p0);
        unsigned b1 = __ballot_sync(0xffffffffu, p1);
        unsigned b2 = __ballot_sync(0xffffffffu, p2);
        int npass = __popc(b0) + __popc(b1) + __popc(b2);
        if (!npass) continue;
        int base = 0;
        if (lane == 0) base = atomicAdd(&g_count[simg], npass);
        base = __shfl_sync(0xffffffffu, base, 0);
        unsigned lt = (1u << lane) - 1u;
        if (p0) {
            int pos = base + __popc(b0 & lt);
            if (pos < KCAP) {
                unsigned flat = (unsigned)(sa * NCLS + c0);
                g_keys[simg][pos] = ((unsigned long long)__float_as_uint(s0) << 32) | (0xFFFFFFFFu - flat);
            }
        }
        if (p1) {
            int pos = base + __popc(b0) + __popc(b1 & lt);
            if (pos < KCAP) {
                unsigned flat = (unsigned)(sa * NCLS + c1);
                g_keys[simg][pos] = ((unsigned long long)__float_as_uint(s1) << 32) | (0xFFFFFFFFu - flat);
            }
        }
        if (p2) {
            int pos = base + __popc(b0) + __popc(b1) + __popc(b2 & lt);
            if (pos < KCAP) {
                unsigned flat = (unsigned)(sa * NCLS + c2);
                g_keys[simg][pos] = ((unsigned long long)__float_as_uint(s2) << 32) | (0xFFFFFFFFu - flat);
            }
        }
    }
}

// ---- bitonic helpers ----
__device__ __forceinline__ void cswap64(unsigned long long& a, unsigned long long& b, bool dir) {
    if ((a > b) == dir) { unsigned long long t = a; a = b; b = t; }
}
__device__ __forceinline__ void cswap32(unsigned& a, unsigned& b, bool dir) {
    if ((a > b) == dir) { unsigned t = a; a = b; b = t; }
}

// u64 stage: all phases j<=64 of stage k, warp owns 128 elems (4/lane, p=base+lane+32m)
__device__ __forceinline__ void local_stage(unsigned long long v[4], int base, int lane, int k) {
    if (k >= 128) {
        bool d0 = (((base + lane)      & k) == 0);
        bool d1 = (((base + lane + 32) & k) == 0);
        cswap64(v[0], v[2], d0);
        cswap64(v[1], v[3], d1);
    }
    if (k >= 64) {
        bool d0 = (((base + lane)      & k) == 0);
        bool d1 = (((base + lane + 64) & k) == 0);
        cswap64(v[0], v[1], d0);
        cswap64(v[2], v[3], d1);
    }
    int jstart = (k >> 1) < 16 ? (k >> 1) : 16;
    for (int j = jstart; j >= 1; j >>= 1) {
#pragma unroll
        for (int m = 0; m < 4; m++) {
            int idx = base + lane + 32 * m;
            unsigned long long other = __shfl_xor_sync(0xffffffffu, v[m], j);
            bool keepmin = (((idx & j) == 0) == ((idx & k) == 0));
            v[m] = keepmin ? (v[m] < other ? v[m] : other)
                           : (v[m] > other ? v[m] : other);
        }
    }
}

// full ascending bitonic sort of 256 u32 values, 8/lane, p = lane + 32*m
__device__ __forceinline__ void sort256(unsigned v[8], int lane) {
    for (int k = 2; k <= 256; k <<= 1) {
        for (int j = k >> 1; j >= 1; j >>= 1) {
            if (j >= 32) {
                int jm = j >> 5;
#pragma unroll
                for (int m = 0; m < 8; m++) {
                    int mp = m ^ jm;
                    if (mp > m) {
                        bool dir = (((lane + 32 * m) & k) == 0);
                        cswap32(v[m], v[mp], dir);
                    }
                }
            } else {
#pragma unroll
                for (int m = 0; m < 8; m++) {
                    int p = lane + 32 * m;
                    unsigned o = __shfl_xor_sync(0xffffffffu, v[m], j);
                    bool keepmin = (((p & j) == 0) == ((p & k) == 0));
                    v[m] = keepmin ? (v[m] < o ? v[m] : o) : (v[m] > o ? v[m] : o);
                }
            }
        }
    }
}

// -------- mega kernel: per-image sort + group + NMS + output, all in smem --------
struct SMem {
    unsigned long long keys[KCAP];      // 32 KB
    float4             box[KCAP];       // 64 KB
    float              score[KCAP];     // 16 KB
    unsigned short     list[KCAP];      //  8 KB
    unsigned char      cls[KCAP];       //  4 KB
    unsigned char      keep[KCAP];      //  4 KB
    int hist[NCLS];
    int start[NCLS + 1];
    int hist2[NCLS];
    int wsums[32];
    int s_off;
};

__global__ void __launch_bounds__(1024, 1) mega_kernel(const float* __restrict__ pred,
                                                       float* __restrict__ out) {
    extern __shared__ char smem_raw[];
    SMem* sm = (SMem*)smem_raw;
    int img  = blockIdx.x;
    int tid  = threadIdx.x;
    int lane = tid & 31;
    int wid  = tid >> 5;
    int base = wid * 128;

    int cnt0 = g_count[img];
    int n    = cnt0 < KCAP ? cnt0 : KCAP;
    if (tid < NCLS) { sm->hist[tid] = 0; sm->hist2[tid] = 0; }

    // ---- phase 1: bitonic sort of inverted keys (ascending) ----
    unsigned long long v[4];
#pragma unroll
    for (int m = 0; m < 4; m++) {
        int idx = base + lane + 32 * m;
        v[m] = (idx < n) ? ~g_keys[img][idx] : ~0ULL;
    }
    for (int k = 2; k <= 64; k <<= 1) local_stage(v, base, lane, k);
#pragma unroll
    for (int m = 0; m < 4; m++) sm->keys[base + lane + 32 * m] = v[m];
    __syncthreads();
    for (int k = 128; k <= KCAP; k <<= 1) {
        for (int j = k >> 1; j >= 128; j >>= 1) {
            for (int t2 = tid; t2 < KCAP / 2; t2 += 1024) {
                int i = ((t2 & ~(j - 1)) << 1) | (t2 & (j - 1));
                int l = i | j;
                unsigned long long a = sm->keys[i], b = sm->keys[l];
                bool dir = ((i & k) == 0);
                if ((a > b) == dir) { sm->keys[i] = b; sm->keys[l] = a; }
            }
            __syncthreads();
        }
#pragma unroll
        for (int m = 0; m < 4; m++) v[m] = sm->keys[base + lane + 32 * m];
        local_stage(v, base, lane, k);
        if (k < KCAP) {
#pragma unroll
            for (int m = 0; m < 4; m++) sm->keys[base + lane + 32 * m] = v[m];
            __syncthreads();
        }
    }

    // ---- phase 2: decode sorted candidates into smem, histogram classes ----
    int carr[4];
#pragma unroll
    for (int m = 0; m < 4; m++) {
        int r = base + lane + 32 * m;
        sm->keep[r] = 0;
        if (r < n) {
            unsigned long long key = ~v[m];
            float score = __uint_as_float((unsigned)(key >> 32));
            unsigned flat = 0xFFFFFFFFu - (unsigned)(key & 0xFFFFFFFFu);
            int a = (int)(flat / NCLS);
            int c = (int)(flat - (unsigned)a * NCLS);
            const float* row = pred + ((long long)img * NANCH + a) * ROWLEN;
            float x = row[0], y = row[1], w = row[2], h = row[3];
            float hw = __fmul_rn(w, 0.5f), hh = __fmul_rn(h, 0.5f);
            float4 bx;
            bx.x = __fsub_rn(x, hw);
            bx.y = __fsub_rn(y, hh);
            bx.z = __fadd_rn(x, hw);
            bx.w = __fadd_rn(y, hh);
            sm->box[r]   = bx;
            sm->score[r] = score;
            sm->cls[r]   = (unsigned char)c;
            carr[m] = c;
            atomicAdd(&sm->hist[c], 1);
        } else {
            sm->score[r] = 0.f;
            sm->cls[r]   = 255;
            carr[m] = -1;
        }
    }
    __syncthreads();
    if (tid == 0) {
        int acc = 0;
        for (int c = 0; c < NCLS; c++) { sm->start[c] = acc; acc += sm->hist[c]; }
        sm->start[NCLS] = acc;
    }
    __syncthreads();
#pragma unroll
    for (int m = 0; m < 4; m++) {
        if (carr[m] >= 0) {
            int c   = carr[m];
            int pos = sm->start[c] + atomicAdd(&sm->hist2[c], 1);
            sm->list[pos] = (unsigned short)(base + lane + 32 * m);
        }
    }
    __syncthreads();

    // ---- phase 3: kept-driven per-class greedy NMS (one warp per class) ----
    for (int c = wid; c < NCLS; c += 32) {
        int st  = sm->start[c];
        int cnt = sm->start[c + 1] - st;
        if (cnt <= 0) continue;
        if (cnt > CLSCAP) cnt = CLSCAP;

        // sort this class's rank list ascending (= descending score order)
        unsigned rv[8];
#pragma unroll
        for (int m = 0; m < 8; m++) {
            int p = lane + 32 * m;
            rv[m] = (p < cnt) ? (unsigned)sm->list[st + p] : 0xFFFFu;
        }
        sort256(rv, lane);
#pragma unroll
        for (int m = 0; m < 8; m++) {
            int p = lane + 32 * m;
            if (p < cnt) sm->list[st + p] = (unsigned short)rv[m];
        }
        __syncwarp();

        float offs = __fmul_rn((float)c, MAXWH);
        unsigned alive = 0;
#pragma unroll
        for (int m = 0; m < 8; m++)
            if (lane + 32 * m < cnt) alive |= (1u << m);

        while (true) {
            int pl = alive ? (lane + 32 * (__ffs(alive) - 1)) : 0x7FFFFFFF;
#pragma unroll
            for (int o = 16; o >= 1; o >>= 1) {
                int x = __shfl_xor_sync(0xffffffffu, pl, o);
                pl = pl < x ? pl : x;
            }
            if (pl == 0x7FFFFFFF) break;
            int p = pl;
            int r = sm->list[st + p];                // LDS broadcast
            if (lane == (p & 31)) alive &= ~(1u << (p >> 5));
            if (lane == 0) sm->keep[r] = 1;

            float4 bb = sm->box[r];
            float ax1 = __fadd_rn(bb.x, offs), ay1 = __fadd_rn(bb.y, offs);
            float ax2 = __fadd_rn(bb.z, offs), ay2 = __fadd_rn(bb.w, offs);
            float areaA = __fmul_rn(__fsub_rn(ax2, ax1), __fsub_rn(ay2, ay1));
#pragma unroll
            for (int m = 0; m < 8; m++) {
                if ((alive >> m) & 1u) {
                    int r2 = sm->list[st + lane + 32 * m];
                    float4 kb = sm->box[r2];
                    float bx1 = __fadd_rn(kb.x, offs), by1 = __fadd_rn(kb.y, offs);
                    float bx2 = __fadd_rn(kb.z, offs), by2 = __fadd_rn(kb.w, offs);
                    float ltx = fmaxf(ax1, bx1), lty = fmaxf(ay1, by1);
                    float rbx = fminf(ax2, bx2), rby = fminf(ay2, by2);
                    float iw = fmaxf(__fsub_rn(rbx, ltx), 0.f);
                    float ih = fmaxf(__fsub_rn(rby, lty), 0.f);
                    float inter = __fmul_rn(iw, ih);
                    float areaB = __fmul_rn(__fsub_rn(bx2, bx1), __fsub_rn(by2, by1));
                    float denom = __fadd_rn(__fsub_rn(__fadd_rn(areaA, areaB), inter), 1e-7f);
                    float iou = __fdiv_rn(inter, denom);
                    if (iou > IOUT) alive &= ~(1u << m);
                }
            }
        }
    }
    __syncthreads();

    // ---- phase 4: compact first 300 kept, write dets + mask ----
    float* dets = out;                          // [B][300][6]
    float* mask = out + BATCH * MAXDET * 6;     // [B][300]
    for (int j = tid; j < MAXDET * 6; j += 1024)
        dets[img * MAXDET * 6 + j] = 0.f;
    if (tid == 0) sm->s_off = 0;
    __syncthreads();

    for (int b2 = 0; b2 < KCAP; b2 += 1024) {
        int idx = b2 + tid;
        int f = sm->keep[idx];
        unsigned bal = __ballot_sync(0xffffffffu, f);
        int prefix = __popc(bal & ((1u << lane) - 1u));
        if (lane == 0) sm->wsums[wid] = __popc(bal);
        __syncthreads();
        int woff = 0;
        for (int w = 0; w < wid; w++) woff += sm->wsums[w];
        int rank = sm->s_off + woff + prefix;
        if (f && rank < MAXDET) {
            float4 bb = sm->box[idx];
            float* d = dets + ((long long)img * MAXDET + rank) * 6;
            d[0] = bb.x; d[1] = bb.y; d[2] = bb.z; d[3] = bb.w;
            d[4] = sm->score[idx];
            d[5] = (float)sm->cls[idx];
        }
        __syncthreads();
        if (tid == 0) {
            int tot = 0;
            for (int w = 0; w < 32; w++) tot += sm->wsums[w];
            sm->s_off += tot;
        }
        __syncthreads();
    }

    int nk = sm->s_off < MAXDET ? sm->s_off : MAXDET;
    for (int j = tid; j < MAXDET; j += 1024)
        mask[img * MAXDET + j] = (j < nk) ? 1.0f : 0.0f;
}

extern "C" void kernel_launch(void* const* d_in, const int* in_sizes, int n_in,
                              void* d_out, int out_size) {
    const float* pred = (const float*)d_in[0];
    float* out = (float*)d_out;
    (void)in_sizes; (void)n_in; (void)out_size;

    void* cnt_addr = nullptr;
    cudaGetSymbolAddress(&cnt_addr, g_count);
    cudaMemsetAsync(cnt_addr, 0, BATCH * sizeof(int));

    filter_kernel<<<(BATCH * NANCH + 255) / 256, 256>>>(pred);

    cudaFuncSetAttribute(mega_kernel, cudaFuncAttributeMaxDynamicSharedMemorySize,
                         (int)sizeof(SMem));
    mega_kernel<<<BATCH, 1024, sizeof(SMem)>>>(pred, out);
}

// round 5
// speedup vs baseline: 1.2082x; 1.2082x over previous
#include <cuda_runtime.h>
#include <stdint.h>

#define BATCH   16
#define NANCH   25200
#define NCLS    80
#define ROWLEN  85
#define KCAP    4096
#define MAXDET  300
#define CONF    0.45f
#define IOUT    0.45f
#define MAXWH   4096.0f
#define CLSCAP  256
#define DEAD    0xFFFFFFFFu

// -------- device scratch --------
__device__ int                g_count[BATCH];
__device__ unsigned long long g_keys[BATCH][KCAP];

// -------- kernel 1: warp-cooperative confidence filter --------
__global__ void __launch_bounds__(256) filter_kernel(const float* __restrict__ pred) {
    int t    = blockIdx.x * blockDim.x + threadIdx.x;
    int lane = threadIdx.x & 31;
    bool valid = t < BATCH * NANCH;
    int img = valid ? t / NANCH : 0;
    int a   = valid ? t - img * NANCH : 0;
    float obj = valid ? pred[(long long)t * ROWLEN + 4] : 0.f;

    unsigned pa = __ballot_sync(0xffffffffu, obj > CONF);
    while (pa) {
        int src = __ffs(pa) - 1;
        pa &= pa - 1;
        int   simg = __shfl_sync(0xffffffffu, img, src);
        int   sa   = __shfl_sync(0xffffffffu, a,   src);
        float sobj = __shfl_sync(0xffffffffu, obj, src);
        const float* row = pred + ((long long)simg * NANCH + sa) * ROWLEN;

        int c0 = lane, c1 = lane + 32, c2 = lane + 64;
        float s0 = __fmul_rn(row[5 + c0], sobj);
        float s1 = __fmul_rn(row[5 + c1], sobj);
        float s2 = (c2 < NCLS) ? __fmul_rn(row[5 + c2], sobj) : 0.f;
        bool p0 = s0 > CONF, p1 = s1 > CONF, p2 = (c2 < NCLS) && (s2 > CONF);
        unsigned b0 = __ballot_sync(0xffffffffu, p0);
        unsigned b1 = __ballot_sync(0xffffffffu, p1);
        unsigned b2 = __ballot_sync(0xffffffffu, p2);
        int npass = __popc(b0) + __popc(b1) + __popc(b2);
        if (!npass) continue;
        int base = 0;
        if (lane == 0) base = atomicAdd(&g_count[simg], npass);
        base = __shfl_sync(0xffffffffu, base, 0);
        unsigned lt = (1u << lane) - 1u;
        if (p0) {
            int pos = base + __popc(b0 & lt);
            if (pos < KCAP) {
                unsigned flat = (unsigned)(sa * NCLS + c0);
                g_keys[simg][pos] = ((unsigned long long)__float_as_uint(s0) << 32) | (0xFFFFFFFFu - flat);
            }
        }
        if (p1) {
            int pos = base + __popc(b0) + __popc(b1 & lt);
            if (pos < KCAP) {
                unsigned flat = (unsigned)(sa * NCLS + c1);
                g_keys[simg][pos] = ((unsigned long long)__float_as_uint(s1) << 32) | (0xFFFFFFFFu - flat);
            }
        }
        if (p2) {
            int pos = base + __popc(b0) + __popc(b1) + __popc(b2 & lt);
            if (pos < KCAP) {
                unsigned flat = (unsigned)(sa * NCLS + c2);
                g_keys[simg][pos] = ((unsigned long long)__float_as_uint(s2) << 32) | (0xFFFFFFFFu - flat);
            }
        }
    }
}

// ---- bitonic helpers (static register indexing ONLY) ----
__device__ __forceinline__ void cswap64(unsigned long long& a, unsigned long long& b, bool dir) {
    if ((a > b) == dir) { unsigned long long t = a; a = b; b = t; }
}

// all phases j<=64 of stage k; warp owns 128 elems (4/lane, p = base+lane+32m)
__device__ __forceinline__ void local_stage(unsigned long long v[4], int base, int lane, int k) {
    if (k >= 128) {
        bool d0 = (((base + lane)      & k) == 0);
        bool d1 = (((base + lane + 32) & k) == 0);
        cswap64(v[0], v[2], d0);
        cswap64(v[1], v[3], d1);
    }
    if (k >= 64) {
        bool d0 = (((base + lane)      & k) == 0);
        bool d1 = (((base + lane + 64) & k) == 0);
        cswap64(v[0], v[1], d0);
        cswap64(v[2], v[3], d1);
    }
    int jstart = (k >> 1) < 16 ? (k >> 1) : 16;
    for (int j = jstart; j >= 1; j >>= 1) {
#pragma unroll
        for (int m = 0; m < 4; m++) {
            int idx = base + lane + 32 * m;
            unsigned long long other = __shfl_xor_sync(0xffffffffu, v[m], j);
            bool keepmin = (((idx & j) == 0) == ((idx & k) == 0));
            v[m] = keepmin ? (v[m] < other ? v[m] : other)
                           : (v[m] > other ? v[m] : other);
        }
    }
}

// -------- mega kernel: per-image sort + group + NMS + output, all in smem --------
struct SMem {
    unsigned long long keys[KCAP];      // 32 KB
    float4             box[KCAP];       // 64 KB
    float              score[KCAP];     // 16 KB
    unsigned short     list[KCAP];      //  8 KB
    unsigned char      cls[KCAP];       //  4 KB
    unsigned char      keep[KCAP];      //  4 KB
    int hist[NCLS];
    int start[NCLS + 1];
    int hist2[NCLS];
    int wsums[32];
    int s_off;
};

__global__ void __launch_bounds__(1024, 1) mega_kernel(const float* __restrict__ pred,
                                                       float* __restrict__ out) {
    extern __shared__ char smem_raw[];
    SMem* sm = (SMem*)smem_raw;
    int img  = blockIdx.x;
    int tid  = threadIdx.x;
    int lane = tid & 31;
    int wid  = tid >> 5;
    int base = wid * 128;

    int cnt0 = g_count[img];
    int n    = cnt0 < KCAP ? cnt0 : KCAP;
    if (tid < NCLS) { sm->hist[tid] = 0; sm->hist2[tid] = 0; }

    // ---- phase 1: bitonic sort of inverted keys (ascending) ----
    unsigned long long v[4];
#pragma unroll
    for (int m = 0; m < 4; m++) {
        int idx = base + lane + 32 * m;
        v[m] = (idx < n) ? ~g_keys[img][idx] : ~0ULL;
    }
    for (int k = 2; k <= 64; k <<= 1) local_stage(v, base, lane, k);
#pragma unroll
    for (int m = 0; m < 4; m++) sm->keys[base + lane + 32 * m] = v[m];
    __syncthreads();
    for (int k = 128; k <= KCAP; k <<= 1) {
        for (int j = k >> 1; j >= 128; j >>= 1) {
            for (int t2 = tid; t2 < KCAP / 2; t2 += 1024) {
                int i = ((t2 & ~(j - 1)) << 1) | (t2 & (j - 1));
                int l = i | j;
                unsigned long long a = sm->keys[i], b = sm->keys[l];
                bool dir = ((i & k) == 0);
                if ((a > b) == dir) { sm->keys[i] = b; sm->keys[l] = a; }
            }
            __syncthreads();
        }
#pragma unroll
        for (int m = 0; m < 4; m++) v[m] = sm->keys[base + lane + 32 * m];
        local_stage(v, base, lane, k);
        if (k < KCAP) {
#pragma unroll
            for (int m = 0; m < 4; m++) sm->keys[base + lane + 32 * m] = v[m];
            __syncthreads();
        }
    }

    // ---- phase 2: decode sorted candidates into smem, histogram classes ----
    int carr[4];
#pragma unroll
    for (int m = 0; m < 4; m++) {
        int r = base + lane + 32 * m;
        sm->keep[r] = 0;
        if (r < n) {
            unsigned long long key = ~v[m];
            float score = __uint_as_float((unsigned)(key >> 32));
            unsigned flat = 0xFFFFFFFFu - (unsigned)(key & 0xFFFFFFFFu);
            int a = (int)(flat / NCLS);
            int c = (int)(flat - (unsigned)a * NCLS);
            const float* row = pred + ((long long)img * NANCH + a) * ROWLEN;
            float x = row[0], y = row[1], w = row[2], h = row[3];
            float hw = __fmul_rn(w, 0.5f), hh = __fmul_rn(h, 0.5f);
            float4 bx;
            bx.x = __fsub_rn(x, hw);
            bx.y = __fsub_rn(y, hh);
            bx.z = __fadd_rn(x, hw);
            bx.w = __fadd_rn(y, hh);
            sm->box[r]   = bx;
            sm->score[r] = score;
            sm->cls[r]   = (unsigned char)c;
            carr[m] = c;
            atomicAdd(&sm->hist[c], 1);
        } else {
            sm->score[r] = 0.f;
            sm->cls[r]   = 255;
            carr[m] = -1;
        }
    }
    __syncthreads();
    if (tid == 0) {
        int acc = 0;
        for (int c = 0; c < NCLS; c++) { sm->start[c] = acc; acc += sm->hist[c]; }
        sm->start[NCLS] = acc;
    }
    __syncthreads();
#pragma unroll
    for (int m = 0; m < 4; m++) {
        if (carr[m] >= 0) {
            int c   = carr[m];
            int pos = sm->start[c] + atomicAdd(&sm->hist2[c], 1);
            sm->list[pos] = (unsigned short)(base + lane + 32 * m);
        }
    }
    __syncthreads();

    // ---- phase 3: per-class greedy NMS via min-rank extraction (one warp/class) ----
    // rank values encode score order (lower rank = higher score); no sorting needed.
    for (int c = wid; c < NCLS; c += 32) {
        int st  = sm->start[c];
        int cnt = sm->start[c + 1] - st;
        if (cnt <= 0) continue;
        if (cnt > CLSCAP) cnt = CLSCAP;

        unsigned rv[8];
#pragma unroll
        for (int m = 0; m < 8; m++) {
            int p = lane + 32 * m;
            rv[m] = (p < cnt) ? (unsigned)sm->list[st + p] : DEAD;
        }

        float offs = __fmul_rn((float)c, MAXWH);
        while (true) {
            unsigned mn = rv[0];
#pragma unroll
            for (int m = 1; m < 8; m++) mn = mn < rv[m] ? mn : rv[m];
#pragma unroll
            for (int o = 16; o >= 1; o >>= 1) {
                unsigned x = __shfl_xor_sync(0xffffffffu, mn, o);
                mn = mn < x ? mn : x;
            }
            if (mn == DEAD) break;
#pragma unroll
            for (int m = 0; m < 8; m++) if (rv[m] == mn) rv[m] = DEAD;
            if (lane == 0) sm->keep[mn] = 1;

            float4 bb = sm->box[mn];
            float ax1 = __fadd_rn(bb.x, offs), ay1 = __fadd_rn(bb.y, offs);
            float ax2 = __fadd_rn(bb.z, offs), ay2 = __fadd_rn(bb.w, offs);
            float areaA = __fmul_rn(__fsub_rn(ax2, ax1), __fsub_rn(ay2, ay1));
#pragma unroll
            for (int m = 0; m < 8; m++) {
                if (rv[m] != DEAD) {
                    float4 kb = sm->box[rv[m]];
                    float bx1 = __fadd_rn(kb.x, offs), by1 = __fadd_rn(kb.y, offs);
                    float bx2 = __fadd_rn(kb.z, offs), by2 = __fadd_rn(kb.w, offs);
                    float ltx = fmaxf(ax1, bx1), lty = fmaxf(ay1, by1);
                    float rbx = fminf(ax2, bx2), rby = fminf(ay2, by2);
                    float iw = fmaxf(__fsub_rn(rbx, ltx), 0.f);
                    float ih = fmaxf(__fsub_rn(rby, lty), 0.f);
                    float inter = __fmul_rn(iw, ih);
                    float areaB = __fmul_rn(__fsub_rn(bx2, bx1), __fsub_rn(by2, by1));
                    float denom = __fadd_rn(__fsub_rn(__fadd_rn(areaA, areaB), inter), 1e-7f);
                    float iou = __fdiv_rn(inter, denom);
                    if (iou > IOUT) rv[m] = DEAD;
                }
            }
        }
    }
    __syncthreads();

    // ---- phase 4: compact first 300 kept, write dets + mask ----
    float* dets = out;                          // [B][300][6]
    float* mask = out + BATCH * MAXDET * 6;     // [B][300]
    for (int j = tid; j < MAXDET * 6; j += 1024)
        dets[img * MAXDET * 6 + j] = 0.f;
    if (tid == 0) sm->s_off = 0;
    __syncthreads();

    for (int b2 = 0; b2 < KCAP; b2 += 1024) {
        int idx = b2 + tid;
        int f = sm->keep[idx];
        unsigned bal = __ballot_sync(0xffffffffu, f);
        int prefix = __popc(bal & ((1u << lane) - 1u));
        if (lane == 0) sm->wsums[wid] = __popc(bal);
        __syncthreads();
        int woff = 0;
        for (int w = 0; w < wid; w++) woff += sm->wsums[w];
        int rank = sm->s_off + woff + prefix;
        if (f && rank < MAXDET) {
            float4 bb = sm->box[idx];
            float* d = dets + ((long long)img * MAXDET + rank) * 6;
            d[0] = bb.x; d[1] = bb.y; d[2] = bb.z; d[3] = bb.w;
            d[4] = sm->score[idx];
            d[5] = (float)sm->cls[idx];
        }
        __syncthreads();
        if (tid == 0) {
            int tot = 0;
            for (int w = 0; w < 32; w++) tot += sm->wsums[w];
            sm->s_off += tot;
        }
        __syncthreads();
    }

    int nk = sm->s_off < MAXDET ? sm->s_off : MAXDET;
    for (int j = tid; j < MAXDET; j += 1024)
        mask[img * MAXDET + j] = (j < nk) ? 1.0f : 0.0f;
}

extern "C" void kernel_launch(void* const* d_in, const int* in_sizes, int n_in,
                              void* d_out, int out_size) {
    const float* pred = (const float*)d_in[0];
    float* out = (float*)d_out;
    (void)in_sizes; (void)n_in; (void)out_size;

    void* cnt_addr = nullptr;
    cudaGetSymbolAddress(&cnt_addr, g_count);
    cudaMemsetAsync(cnt_addr, 0, BATCH * sizeof(int));

    filter_kernel<<<(BATCH * NANCH + 255) / 256, 256>>>(pred);

    cudaFuncSetAttribute(mega_kernel, cudaFuncAttributeMaxDynamicSharedMemorySize,
                         (int)sizeof(SMem));
    mega_kernel<<<BATCH, 1024, sizeof(SMem)>>>(pred, out);
}

// round 6
// speedup vs baseline: 1.6246x; 1.3447x over previous
#include <cuda_runtime.h>
#include <stdint.h>

#define BATCH   16
#define NANCH   25200
#define NCLS    80
#define ROWLEN  85
#define KCAP    4096
#define MAXDET  300
#define CONF    0.45f
#define IOUT    0.45f
#define MAXWH   4096.0f
#define CLSCAP  256
#define DEADU   0xFFFFFFFFu

// -------- device scratch --------
__device__ int                g_count[BATCH];
__device__ unsigned long long g_keys[BATCH][KCAP];
__device__ float4             g_box[BATCH][KCAP];
__device__ float              g_score[BATCH][KCAP];
__device__ unsigned char      g_cls[BATCH][KCAP];
__device__ unsigned char      g_keep[BATCH][KCAP];
__device__ unsigned short     g_list[BATCH][KCAP];
__device__ int                g_clsOff[BATCH][NCLS + 1];

// -------- kernel 1: confidence filter (round-3 measured version) --------
__global__ void filter_kernel(const float* __restrict__ pred) {
    int t = blockIdx.x * blockDim.x + threadIdx.x;
    if (t >= BATCH * NANCH) return;
    int img = t / NANCH;
    int a   = t - img * NANCH;
    const float* row = pred + (long long)t * ROWLEN;
    float obj = row[4];
    if (obj <= CONF) return;
#pragma unroll 4
    for (int c = 0; c < NCLS; c++) {
        float s = __fmul_rn(row[5 + c], obj);
        if (s > CONF) {
            unsigned flat = (unsigned)(a * NCLS + c);
            unsigned long long key =
                ((unsigned long long)__float_as_uint(s) << 32) | (0xFFFFFFFFu - flat);
            int pos = atomicAdd(&g_count[img], 1);
            if (pos < KCAP) g_keys[img][pos] = key;
        }
    }
}

// ---- u64 bitonic helpers (static register indexing only) ----
__device__ __forceinline__ void cswap64(unsigned long long& a, unsigned long long& b, bool dir) {
    if ((a > b) == dir) { unsigned long long t = a; a = b; b = t; }
}
__device__ __forceinline__ void local_stage(unsigned long long v[4], int base, int lane, int k) {
    if (k >= 128) {
        bool d0 = (((base + lane)      & k) == 0);
        bool d1 = (((base + lane + 32) & k) == 0);
        cswap64(v[0], v[2], d0);
        cswap64(v[1], v[3], d1);
    }
    if (k >= 64) {
        bool d0 = (((base + lane)      & k) == 0);
        bool d1 = (((base + lane + 64) & k) == 0);
        cswap64(v[0], v[1], d0);
        cswap64(v[2], v[3], d1);
    }
    int jstart = (k >> 1) < 16 ? (k >> 1) : 16;
    for (int j = jstart; j >= 1; j >>= 1) {
#pragma unroll
        for (int m = 0; m < 4; m++) {
            int idx = base + lane + 32 * m;
            unsigned long long other = __shfl_xor_sync(0xffffffffu, v[m], j);
            bool keepmin = (((idx & j) == 0) == ((idx & k) == 0));
            v[m] = keepmin ? (v[m] < other ? v[m] : other)
                           : (v[m] > other ? v[m] : other);
        }
    }
}

// -------- kernel 2: per-image bitonic sort + decode + class grouping --------
__global__ void sort_kernel(const float* __restrict__ pred) {
    __shared__ unsigned long long s[KCAP];   // 32 KB
    __shared__ int hist[NCLS], start[NCLS + 1], hist2[NCLS];
    int img  = blockIdx.x;
    int tid  = threadIdx.x;                  // 1024
    int lane = tid & 31;
    int base = (tid >> 5) * 128;
    int cnt  = g_count[img];
    int n    = cnt < KCAP ? cnt : KCAP;
    if (tid < NCLS) { hist[tid] = 0; hist2[tid] = 0; }

    unsigned long long v[4];
#pragma unroll
    for (int m = 0; m < 4; m++) {
        int idx = base + lane + 32 * m;
        v[m] = (idx < n) ? ~g_keys[img][idx] : ~0ULL;
    }
    for (int k = 2; k <= 64; k <<= 1) local_stage(v, base, lane, k);
#pragma unroll
    for (int m = 0; m < 4; m++) s[base + lane + 32 * m] = v[m];
    __syncthreads();
    for (int k = 128; k <= KCAP; k <<= 1) {
        for (int j = k >> 1; j >= 128; j >>= 1) {
            for (int t2 = tid; t2 < KCAP / 2; t2 += 1024) {
                int i = ((t2 & ~(j - 1)) << 1) | (t2 & (j - 1));
                int l = i | j;
                unsigned long long a = s[i], b = s[l];
                bool dir = ((i & k) == 0);
                if ((a > b) == dir) { s[i] = b; s[l] = a; }
            }
            __syncthreads();
        }
#pragma unroll
        for (int m = 0; m < 4; m++) v[m] = s[base + lane + 32 * m];
        local_stage(v, base, lane, k);
        if (k < KCAP) {
#pragma unroll
            for (int m = 0; m < 4; m++) s[base + lane + 32 * m] = v[m];
            __syncthreads();
        }
    }

    // decode + histogram
    int carr[4];
#pragma unroll
    for (int m = 0; m < 4; m++) {
        int r = base + lane + 32 * m;
        g_keep[img][r] = 0;
        if (r < n) {
            unsigned long long key = ~v[m];
            float score = __uint_as_float((unsigned)(key >> 32));
            unsigned flat = 0xFFFFFFFFu - (unsigned)(key & 0xFFFFFFFFu);
            int a = (int)(flat / NCLS);
            int c = (int)(flat - (unsigned)a * NCLS);
            const float* row = pred + ((long long)img * NANCH + a) * ROWLEN;
            float x = row[0], y = row[1], w = row[2], h = row[3];
            float hw = __fmul_rn(w, 0.5f), hh = __fmul_rn(h, 0.5f);
            float4 bx;
            bx.x = __fsub_rn(x, hw);
            bx.y = __fsub_rn(y, hh);
            bx.z = __fadd_rn(x, hw);
            bx.w = __fadd_rn(y, hh);
            g_box[img][r]   = bx;
            g_score[img][r] = score;
            g_cls[img][r]   = (unsigned char)c;
            carr[m] = c;
            atomicAdd(&hist[c], 1);
        } else {
            g_score[img][r] = 0.f;
            g_cls[img][r]   = 255;
            carr[m] = -1;
        }
    }
    __syncthreads();
    if (tid == 0) {
        int acc = 0;
        for (int c = 0; c < NCLS; c++) { start[c] = acc; acc += hist[c]; }
        start[NCLS] = acc;
    }
    __syncthreads();
    if (tid <= NCLS) g_clsOff[img][tid] = start[tid];
#pragma unroll
    for (int m = 0; m < 4; m++) {
        if (carr[m] >= 0) {
            int c   = carr[m];
            int pos = start[c] + atomicAdd(&hist2[c], 1);
            g_list[img][pos] = (unsigned short)(base + lane + 32 * m);
        }
    }
}

// ---- fully static 256-wide warp bitonic sort (8 scalar regs, no arrays) ----
__device__ __forceinline__ void cswap32(unsigned& a, unsigned& b, bool dir) {
    if ((a > b) == dir) { unsigned t = a; a = b; b = t; }
}
#define SHPH(qm, M)                                                          \
    {                                                                        \
        unsigned o = __shfl_xor_sync(0xffffffffu, qm, j);                    \
        bool dir = (((lane + 32 * (M)) & k) == 0);                           \
        bool keepmin = (((lane & j) == 0) == dir);                           \
        qm = keepmin ? (qm < o ? qm : o) : (qm > o ? qm : o);                \
    }
__device__ __forceinline__ void sort256_asc(
    unsigned& q0, unsigned& q1, unsigned& q2, unsigned& q3,
    unsigned& q4, unsigned& q5, unsigned& q6, unsigned& q7, int lane) {
    for (int k = 2; k <= 256; k <<= 1) {
        if (k >= 256) {   // j = 128: pairs (m, m+4)
            cswap32(q0, q4, ((lane      ) & k) == 0);
            cswap32(q1, q5, ((lane +  32) & k) == 0);
            cswap32(q2, q6, ((lane +  64) & k) == 0);
            cswap32(q3, q7, ((lane +  96) & k) == 0);
        }
        if (k >= 128) {   // j = 64: pairs (m, m+2)
            cswap32(q0, q2, ((lane      ) & k) == 0);
            cswap32(q1, q3, ((lane +  32) & k) == 0);
            cswap32(q4, q6, ((lane + 128) & k) == 0);
            cswap32(q5, q7, ((lane + 160) & k) == 0);
        }
        if (k >= 64) {    // j = 32: pairs (m, m+1)
            cswap32(q0, q1, ((lane      ) & k) == 0);
            cswap32(q2, q3, ((lane +  64) & k) == 0);
            cswap32(q4, q5, ((lane + 128) & k) == 0);
            cswap32(q6, q7, ((lane + 192) & k) == 0);
        }
        int jstart = (k >> 1) < 16 ? (k >> 1) : 16;
        for (int j = jstart; j >= 1; j >>= 1) {
            SHPH(q0, 0) SHPH(q1, 1) SHPH(q2, 2) SHPH(q3, 3)
            SHPH(q4, 4) SHPH(q5, 5) SHPH(q6, 6) SHPH(q7, 7)
        }
    }
}

// -------- kernel 3: sorted-bitmask NMS, one warp per (image,class) --------
// smem per warp: 256 float4 offset boxes (4KB) + 256x8 u32 sup rows (8KB)
__global__ void __launch_bounds__(128) nms_kernel() {
    extern __shared__ char sraw[];
    int wp   = threadIdx.x >> 5;
    int lane = threadIdx.x & 31;
    float4*   B = (float4*)sraw + wp * CLSCAP;
    unsigned* R = (unsigned*)(sraw + 4 * CLSCAP * 16) + wp * CLSCAP * 8;
    int task = blockIdx.x * 4 + wp;
    if (task >= BATCH * NCLS) return;
    int img = task / NCLS;
    int cls = task - img * NCLS;
    int st  = g_clsOff[img][cls];
    int cnt = g_clsOff[img][cls + 1] - st;
    if (cnt <= 0) return;
    if (cnt > CLSCAP) cnt = CLSCAP;

    // load ranks (8/lane) and sort ascending = score-descending order
    unsigned q0, q1, q2, q3, q4, q5, q6, q7;
#define LDQ(qm, M) qm = (lane + 32 * (M) < cnt) ? (unsigned)g_list[img][st + lane + 32 * (M)] : DEADU;
    LDQ(q0, 0) LDQ(q1, 1) LDQ(q2, 2) LDQ(q3, 3)
    LDQ(q4, 4) LDQ(q5, 5) LDQ(q6, 6) LDQ(q7, 7)
#undef LDQ
    sort256_asc(q0, q1, q2, q3, q4, q5, q6, q7, lane);

    // stage offset boxes (sentinel for padding -> IoU exactly 0)
    float offs = __fmul_rn((float)cls, MAXWH);
#define STB(qm, M)                                                            \
    {                                                                         \
        int p = lane + 32 * (M);                                              \
        if (p < cnt) {                                                        \
            float4 b = g_box[img][qm];                                        \
            B[p] = make_float4(__fadd_rn(b.x, offs), __fadd_rn(b.y, offs),    \
                               __fadd_rn(b.z, offs), __fadd_rn(b.w, offs));   \
        } else {                                                              \
            B[p] = make_float4(-1e30f, -1e30f, -1e30f, -1e30f);               \
        }                                                                     \
    }
    STB(q0, 0) STB(q1, 1) STB(q2, 2) STB(q3, 3)
    STB(q4, 4) STB(q5, 5) STB(q6, 6) STB(q7, 7)
#undef STB
    __syncwarp();

    // build suppression rows (lane owns rows p = lane+32m)
    int W = (cnt + 31) >> 5;
#pragma unroll
    for (int m = 0; m < 8; m++) {
        int p = lane + 32 * m;
        if (p < cnt) {
            float4 a = B[p];
            float areaA = __fmul_rn(__fsub_rn(a.z, a.x), __fsub_rn(a.w, a.y));
            for (int w = 0; w < W; w++) {
                unsigned bits = 0;
#pragma unroll
                for (int b = 0; b < 32; b++) {
                    float4 kb = B[32 * w + b];          // lane-uniform -> broadcast
                    float ltx = fmaxf(a.x, kb.x), lty = fmaxf(a.y, kb.y);
                    float rbx = fminf(a.z, kb.z), rby = fminf(a.w, kb.w);
                    float iw = fmaxf(__fsub_rn(rbx, ltx), 0.f);
                    float ih = fmaxf(__fsub_rn(rby, lty), 0.f);
                    float inter = __fmul_rn(iw, ih);
                    float areaB = __fmul_rn(__fsub_rn(kb.z, kb.x), __fsub_rn(kb.w, kb.y));
                    float denom = __fadd_rn(__fsub_rn(__fadd_rn(areaA, areaB), inter), 1e-7f);
                    float iou = __fdiv_rn(inter, denom);
                    if (iou > IOUT) bits |= (1u << b);
                }
                R[p * 8 + w] = bits;
            }
        }
    }
    __syncwarp();

    // greedy scan: pure word-mask ops, all lanes in lockstep
#define AL(w) ((cnt >= 32 * ((w) + 1)) ? 0xFFFFFFFFu : ((cnt > 32 * (w)) ? ((1u << (cnt - 32 * (w))) - 1u) : 0u))
    unsigned a0 = AL(0), a1 = AL(1), a2 = AL(2), a3 = AL(3);
    unsigned a4 = AL(4), a5 = AL(5), a6 = AL(6), a7 = AL(7);
#undef AL
    unsigned k0 = 0, k1 = 0, k2 = 0, k3 = 0, k4 = 0, k5 = 0, k6 = 0, k7 = 0;
    while (true) {
        int i;
        if      (a0) { i = __ffs(a0) - 1;        a0 &= a0 - 1; k0 |= 1u << i; }
        else if (a1) { i = __ffs(a1) - 1;        a1 &= a1 - 1; k1 |= 1u << i; i += 32; }
        else if (a2) { i = __ffs(a2) - 1;        a2 &= a2 - 1; k2 |= 1u << i; i += 64; }
        else if (a3) { i = __ffs(a3) - 1;        a3 &= a3 - 1; k3 |= 1u << i; i += 96; }
        else if (a4) { i = __ffs(a4) - 1;        a4 &= a4 - 1; k4 |= 1u << i; i += 128; }
        else if (a5) { i = __ffs(a5) - 1;        a5 &= a5 - 1; k5 |= 1u << i; i += 160; }
        else if (a6) { i = __ffs(a6) - 1;        a6 &= a6 - 1; k6 |= 1u << i; i += 192; }
        else if (a7) { i = __ffs(a7) - 1;        a7 &= a7 - 1; k7 |= 1u << i; i += 224; }
        else break;
        const unsigned* row = &R[i * 8];
        a0 &= ~row[0]; a1 &= ~row[1]; a2 &= ~row[2]; a3 &= ~row[3];
        a4 &= ~row[4]; a5 &= ~row[5]; a6 &= ~row[6]; a7 &= ~row[7];
    }

    // lane writes keep flags for its owned sorted positions
#define WRK(qm, km, M) if (((km) >> lane) & 1u) g_keep[img][qm] = 1;
    WRK(q0, k0, 0) WRK(q1, k1, 1) WRK(q2, k2, 2) WRK(q3, k3, 3)
    WRK(q4, k4, 4) WRK(q5, k5, 5) WRK(q6, k6, 6) WRK(q7, k7, 7)
#undef WRK
}

// -------- kernel 4: compact first 300 kept per image --------
__global__ void output_kernel(float* __restrict__ out) {
    int img  = blockIdx.x;
    int tid  = threadIdx.x;          // 256
    int lane = tid & 31, warp = tid >> 5;
    __shared__ int wsums[8];
    __shared__ int s_off;

    float* dets = out;                           // [B][300][6]
    float* mask = out + BATCH * MAXDET * 6;      // [B][300]

    for (int j = tid; j < MAXDET * 6; j += 256)
        dets[img * MAXDET * 6 + j] = 0.f;
    if (tid == 0) s_off = 0;
    __syncthreads();

    for (int base = 0; base < KCAP; base += 256) {
        int idx = base + tid;
        int f = g_keep[img][idx];
        unsigned bal = __ballot_sync(0xffffffffu, f);
        int prefix = __popc(bal & ((1u << lane) - 1u));
        if (lane == 0) wsums[warp] = __popc(bal);
        __syncthreads();
        int woff = 0;
        for (int w = 0; w < warp; w++) woff += wsums[w];
        int rank = s_off + woff + prefix;
        if (f && rank < MAXDET) {
            float4 bb = g_box[img][idx];
            float* d = dets + ((long long)img * MAXDET + rank) * 6;
            d[0] = bb.x; d[1] = bb.y; d[2] = bb.z; d[3] = bb.w;
            d[4] = g_score[img][idx];
            d[5] = (float)g_cls[img][idx];
        }
        __syncthreads();
        if (tid == 0) {
            int tot = 0;
            for (int w = 0; w < 8; w++) tot += wsums[w];
            s_off += tot;
        }
        __syncthreads();
    }

    int nk = s_off < MAXDET ? s_off : MAXDET;
    for (int j = tid; j < MAXDET; j += 256)
        mask[img * MAXDET + j] = (j < nk) ? 1.0f : 0.0f;
}

extern "C" void kernel_launch(void* const* d_in, const int* in_sizes, int n_in,
                              void* d_out, int out_size) {
    const float* pred = (const float*)d_in[0];
    float* out = (float*)d_out;
    (void)in_sizes; (void)n_in; (void)out_size;

    void* cnt_addr = nullptr;
    cudaGetSymbolAddress(&cnt_addr, g_count);
    cudaMemsetAsync(cnt_addr, 0, BATCH * sizeof(int));

    filter_kernel<<<(BATCH * NANCH + 255) / 256, 256>>>(pred);
    sort_kernel<<<BATCH, 1024>>>(pred);

    int nms_smem = 4 * CLSCAP * 16 + 4 * CLSCAP * 8 * 4;   // 48 KB
    cudaFuncSetAttribute(nms_kernel, cudaFuncAttributeMaxDynamicSharedMemorySize, nms_smem);
    nms_kernel<<<(BATCH * NCLS + 3) / 4, 128, nms_smem>>>();

    output_kernel<<<BATCH, 256>>>(out);
}

// round 8
// speedup vs baseline: 1.9827x; 1.2205x over previous
#include <cuda_runtime.h>
#include <stdint.h>

#define BATCH   16
#define NANCH   25200
#define NCLS    80
#define ROWLEN  85
#define MAXDET  300
#define CONF    0.45f
#define IOUT    0.45f
#define MAXWH   4096.0f
#define CLSCAP  256      // per-(image,class) candidate cap (avg ~30)
#define KEPTCAP 4096     // per-image kept cap (typ ~2200)

// -------- device scratch --------
// counters: [0, BATCH*NCLS) = per-(img,cls) bucket counts; [BATCH*NCLS, +BATCH) = kept counts
__device__ int                g_cnts[BATCH * NCLS + BATCH];
__device__ unsigned long long g_bucket[BATCH][NCLS][CLSCAP];
__device__ unsigned long long g_kept[BATCH][KEPTCAP];

// -------- kernel 1: confidence filter -> per-class buckets --------
__global__ void filter_kernel(const float* __restrict__ pred) {
    int t = blockIdx.x * blockDim.x + threadIdx.x;
    if (t >= BATCH * NANCH) return;
    int img = t / NANCH;
    int a   = t - img * NANCH;
    const float* row = pred + (long long)t * ROWLEN;
    float obj = row[4];
    if (obj <= CONF) return;          // score = cls*obj <= obj: exact gate
#pragma unroll 4
    for (int c = 0; c < NCLS; c++) {
        float s = __fmul_rn(row[5 + c], obj);
        if (s > CONF) {
            unsigned flat = (unsigned)(a * NCLS + c);
            // key: descending score, then ascending flat (jax top_k tie rule)
            unsigned long long key =
                ((unsigned long long)__float_as_uint(s) << 32) | (0xFFFFFFFFu - flat);
            int pos = atomicAdd(&g_cnts[img * NCLS + c], 1);
            if (pos < CLSCAP) g_bucket[img][c][pos] = key;
        }
    }
}

// ---- fully static 256-wide warp bitonic sort of u64 (ascending), 8 scalars ----
__device__ __forceinline__ void cswap64(unsigned long long& a, unsigned long long& b, bool dir) {
    if ((a > b) == dir) { unsigned long long t = a; a = b; b = t; }
}
#define SHPH64(qm, M)                                                         \
    {                                                                         \
        unsigned long long o = __shfl_xor_sync(0xffffffffu, qm, j);           \
        bool dir = (((lane + 32 * (M)) & k) == 0);                            \
        bool keepmin = (((lane & j) == 0) == dir);                            \
        qm = keepmin ? (qm < o ? qm : o) : (qm > o ? qm : o);                 \
    }
__device__ __forceinline__ void sort256_u64(
    unsigned long long& q0, unsigned long long& q1,
    unsigned long long& q2, unsigned long long& q3,
    unsigned long long& q4, unsigned long long& q5,
    unsigned long long& q6, unsigned long long& q7, int lane) {
    for (int k = 2; k <= 256; k <<= 1) {
        if (k >= 256) {   // j = 128
            cswap64(q0, q4, ((lane      ) & k) == 0);
            cswap64(q1, q5, ((lane +  32) & k) == 0);
            cswap64(q2, q6, ((lane +  64) & k) == 0);
            cswap64(q3, q7, ((lane +  96) & k) == 0);
        }
        if (k >= 128) {   // j = 64
            cswap64(q0, q2, ((lane      ) & k) == 0);
            cswap64(q1, q3, ((lane +  32) & k) == 0);
            cswap64(q4, q6, ((lane + 128) & k) == 0);
            cswap64(q5, q7, ((lane + 160) & k) == 0);
        }
        if (k >= 64) {    // j = 32
            cswap64(q0, q1, ((lane      ) & k) == 0);
            cswap64(q2, q3, ((lane +  64) & k) == 0);
            cswap64(q4, q5, ((lane + 128) & k) == 0);
            cswap64(q6, q7, ((lane + 192) & k) == 0);
        }
        int jstart = (k >> 1) < 16 ? (k >> 1) : 16;
        for (int j = jstart; j >= 1; j >>= 1) {
            SHPH64(q0, 0) SHPH64(q1, 1) SHPH64(q2, 2) SHPH64(q3, 3)
            SHPH64(q4, 4) SHPH64(q5, 5) SHPH64(q6, 6) SHPH64(q7, 7)
        }
    }
}

// -------- kernel 2: per-(image,class) NMS, one warp each --------
__global__ void __launch_bounds__(128) nms_kernel(const float* __restrict__ pred) {
    extern __shared__ char sraw[];
    int wp   = threadIdx.x >> 5;
    int lane = threadIdx.x & 31;
    float4*   B = (float4*)sraw + wp * CLSCAP;                            // 16 KB
    unsigned* R = (unsigned*)(sraw + 4 * CLSCAP * 16) + wp * CLSCAP * 8;  // 32 KB
    int task = blockIdx.x * 4 + wp;
    if (task >= BATCH * NCLS) return;
    int img = task / NCLS;
    int cls = task - img * NCLS;
    int cnt = g_cnts[img * NCLS + cls];
    if (cnt <= 0) return;
    if (cnt > CLSCAP) cnt = CLSCAP;

    // load inverted keys (ascending sort => descending score); pad ~0 sorts last
    unsigned long long q0, q1, q2, q3, q4, q5, q6, q7;
#define LDQ(qm, M) qm = (lane + 32 * (M) < cnt) ? ~g_bucket[img][cls][lane + 32 * (M)] : ~0ULL;
    LDQ(q0, 0) LDQ(q1, 1) LDQ(q2, 2) LDQ(q3, 3)
    LDQ(q4, 4) LDQ(q5, 5) LDQ(q6, 6) LDQ(q7, 7)
#undef LDQ
    sort256_u64(q0, q1, q2, q3, q4, q5, q6, q7, lane);

    // stage offset boxes (sentinel for padding -> IoU exactly 0)
    float offs = __fmul_rn((float)cls, MAXWH);
#define STB(qm, M)                                                            \
    {                                                                         \
        int p = lane + 32 * (M);                                              \
        if (p < cnt) {                                                        \
            unsigned long long key = ~(qm);                                   \
            unsigned flat = 0xFFFFFFFFu - (unsigned)(key & 0xFFFFFFFFu);      \
            int a = (int)(flat / NCLS);                                       \
            const float* row = pred + ((long long)img * NANCH + a) * ROWLEN;  \
            float x = row[0], y = row[1], w = row[2], h = row[3];             \
            float hw = __fmul_rn(w, 0.5f), hh = __fmul_rn(h, 0.5f);           \
            B[p] = make_float4(__fadd_rn(__fsub_rn(x, hw), offs),             \
                               __fadd_rn(__fsub_rn(y, hh), offs),             \
                               __fadd_rn(__fadd_rn(x, hw), offs),             \
                               __fadd_rn(__fadd_rn(y, hh), offs));            \
        } else {                                                              \
            B[p] = make_float4(-1e30f, -1e30f, -1e30f, -1e30f);               \
        }                                                                     \
    }
    STB(q0, 0) STB(q1, 1) STB(q2, 2) STB(q3, 3)
    STB(q4, 4) STB(q5, 5) STB(q6, 6) STB(q7, 7)
#undef STB
    __syncwarp();

    // suppression rows: lane owns rows p = lane + 32m
    int W = (cnt + 31) >> 5;
#pragma unroll
    for (int m = 0; m < 8; m++) {
        int p = lane + 32 * m;
        if (p < cnt) {
            float4 a = B[p];
            float areaA = __fmul_rn(__fsub_rn(a.z, a.x), __fsub_rn(a.w, a.y));
            for (int w = 0; w < W; w++) {
                unsigned bits = 0;
#pragma unroll
                for (int b = 0; b < 32; b++) {
                    float4 kb = B[32 * w + b];          // lane-uniform broadcast
                    float ltx = fmaxf(a.x, kb.x), lty = fmaxf(a.y, kb.y);
                    float rbx = fminf(a.z, kb.z), rby = fminf(a.w, kb.w);
                    float iw = fmaxf(__fsub_rn(rbx, ltx), 0.f);
                    float ih = fmaxf(__fsub_rn(rby, lty), 0.f);
                    float inter = __fmul_rn(iw, ih);
                    float areaB = __fmul_rn(__fsub_rn(kb.z, kb.x), __fsub_rn(kb.w, kb.y));
                    float denom = __fadd_rn(__fsub_rn(__fadd_rn(areaA, areaB), inter), 1e-7f);
                    float iou = __fdiv_rn(inter, denom);
                    if (iou > IOUT) bits |= (1u << b);
                }
                R[p * 8 + w] = bits;
            }
        }
    }
    __syncwarp();

    // greedy scan (lockstep, pure word-mask ops)
#define AL(w) ((cnt >= 32 * ((w) + 1)) ? 0xFFFFFFFFu : ((cnt > 32 * (w)) ? ((1u << (cnt - 32 * (w))) - 1u) : 0u))
    unsigned a0 = AL(0), a1 = AL(1), a2 = AL(2), a3 = AL(3);
    unsigned a4 = AL(4), a5 = AL(5), a6 = AL(6), a7 = AL(7);
#undef AL
    unsigned k0 = 0, k1 = 0, k2 = 0, k3 = 0, k4 = 0, k5 = 0, k6 = 0, k7 = 0;
    while (true) {
        int i;
        if      (a0) { i = __ffs(a0) - 1; a0 &= a0 - 1; k0 |= 1u << i; }
        else if (a1) { i = __ffs(a1) - 1; a1 &= a1 - 1; k1 |= 1u << i; i += 32; }
        else if (a2) { i = __ffs(a2) - 1; a2 &= a2 - 1; k2 |= 1u << i; i += 64; }
        else if (a3) { i = __ffs(a3) - 1; a3 &= a3 - 1; k3 |= 1u << i; i += 96; }
        else if (a4) { i = __ffs(a4) - 1; a4 &= a4 - 1; k4 |= 1u << i; i += 128; }
        else if (a5) { i = __ffs(a5) - 1; a5 &= a5 - 1; k5 |= 1u << i; i += 160; }
        else if (a6) { i = __ffs(a6) - 1; a6 &= a6 - 1; k6 |= 1u << i; i += 192; }
        else if (a7) { i = __ffs(a7) - 1; a7 &= a7 - 1; k7 |= 1u << i; i += 224; }
        else break;
        const unsigned* row = &R[i * 8];
        a0 &= ~row[0]; a1 &= ~row[1]; a2 &= ~row[2]; a3 &= ~row[3];
        a4 &= ~row[4]; a5 &= ~row[5]; a6 &= ~row[6]; a7 &= ~row[7];
    }

    // append kept keys (original, non-inverted) to per-image list
    int tot = __popc(k0) + __popc(k1) + __popc(k2) + __popc(k3)
            + __popc(k4) + __popc(k5) + __popc(k6) + __popc(k7);
    if (tot == 0) return;
    int basek = 0;
    if (lane == 0) basek = atomicAdd(&g_cnts[BATCH * NCLS + img], tot);
    basek = __shfl_sync(0xffffffffu, basek, 0);
    unsigned lt = (1u << lane) - 1u;
    int pre = 0;
#define WRK(qm, km, M)                                                        \
    {                                                                         \
        if (((km) >> lane) & 1u) {                                            \
            int pos = basek + pre + __popc((km) & lt);                        \
            if (pos < KEPTCAP) g_kept[img][pos] = ~(qm);                      \
        }                                                                     \
        pre += __popc(km);                                                    \
    }
    WRK(q0, k0, 0) WRK(q1, k1, 1) WRK(q2, k2, 2) WRK(q3, k3, 3)
    WRK(q4, k4, 4) WRK(q5, k5, 5) WRK(q6, k6, 6) WRK(q7, k7, 7)
#undef WRK
}

// ---- u64 bitonic block-sort helpers (round-5 proven) ----
__device__ __forceinline__ void local_stage(unsigned long long v[4], int base, int lane, int k) {
    if (k >= 128) {
        bool d0 = (((base + lane)      & k) == 0);
        bool d1 = (((base + lane + 32) & k) == 0);
        cswap64(v[0], v[2], d0);
        cswap64(v[1], v[3], d1);
    }
    if (k >= 64) {
        bool d0 = (((base + lane)      & k) == 0);
        bool d1 = (((base + lane + 64) & k) == 0);
        cswap64(v[0], v[1], d0);
        cswap64(v[2], v[3], d1);
    }
    int jstart = (k >> 1) < 16 ? (k >> 1) : 16;
    for (int j = jstart; j >= 1; j >>= 1) {
#pragma unroll
        for (int m = 0; m < 4; m++) {
            int idx = base + lane + 32 * m;
            unsigned long long other = __shfl_xor_sync(0xffffffffu, v[m], j);
            bool keepmin = (((idx & j) == 0) == ((idx & k) == 0));
            v[m] = keepmin ? (v[m] < other ? v[m] : other)
                           : (v[m] > other ? v[m] : other);
        }
    }
}

// -------- kernel 3: sort kept keys (<=4096), decode top-300, write dets + mask --------
__global__ void __launch_bounds__(1024) output_kernel(const float* __restrict__ pred,
                                                      float* __restrict__ out) {
    __shared__ unsigned long long s[KEPTCAP];    // 32 KB
    int img  = blockIdx.x;
    int tid  = threadIdx.x;                      // 1024
    int lane = tid & 31;
    int base = (tid >> 5) * 128;

    int nk_all = g_cnts[BATCH * NCLS + img];
    if (nk_all > KEPTCAP) nk_all = KEPTCAP;

    unsigned long long v[4];
#pragma unroll
    for (int m = 0; m < 4; m++) {
        int idx = base + lane + 32 * m;
        v[m] = (idx < nk_all) ? ~g_kept[img][idx] : ~0ULL;
    }
    for (int k = 2; k <= 64; k <<= 1) local_stage(v, base, lane, k);
#pragma unroll
    for (int m = 0; m < 4; m++) s[base + lane + 32 * m] = v[m];
    __syncthreads();
    for (int k = 128; k <= KEPTCAP; k <<= 1) {
        for (int j = k >> 1; j >= 128; j >>= 1) {
            for (int t2 = tid; t2 < KEPTCAP / 2; t2 += 1024) {
                int i = ((t2 & ~(j - 1)) << 1) | (t2 & (j - 1));
                int l = i | j;
                unsigned long long a = s[i], b = s[l];
                bool dir = ((i & k) == 0);
                if ((a > b) == dir) { s[i] = b; s[l] = a; }
            }
            __syncthreads();
        }
#pragma unroll
        for (int m = 0; m < 4; m++) v[m] = s[base + lane + 32 * m];
        local_stage(v, base, lane, k);
#pragma unroll
        for (int m = 0; m < 4; m++) s[base + lane + 32 * m] = v[m];
        __syncthreads();
    }

    int nk = nk_all < MAXDET ? nk_all : MAXDET;
    float* dets = out;                           // [B][300][6]
    float* mask = out + BATCH * MAXDET * 6;      // [B][300]

    for (int r = tid; r < MAXDET; r += 1024) {
        float* d = dets + ((long long)img * MAXDET + r) * 6;
        if (r < nk) {
            unsigned long long key = ~s[r];
            float score  = __uint_as_float((unsigned)(key >> 32));
            unsigned flat = 0xFFFFFFFFu - (unsigned)(key & 0xFFFFFFFFu);
            int a = (int)(flat / NCLS);
            int c = (int)(flat - (unsigned)a * NCLS);
            const float* row = pred + ((long long)img * NANCH + a) * ROWLEN;
            float x = row[0], y = row[1], w = row[2], h = row[3];
            float hw = __fmul_rn(w, 0.5f), hh = __fmul_rn(h, 0.5f);
            d[0] = __fsub_rn(x, hw);
            d[1] = __fsub_rn(y, hh);
            d[2] = __fadd_rn(x, hw);
            d[3] = __fadd_rn(y, hh);
            d[4] = score;
            d[5] = (float)c;
        } else {
            d[0] = 0.f; d[1] = 0.f; d[2] = 0.f; d[3] = 0.f; d[4] = 0.f; d[5] = 0.f;
        }
        mask[img * MAXDET + r] = (r < nk) ? 1.0f : 0.0f;
    }
}

extern "C" void kernel_launch(void* const* d_in, const int* in_sizes, int n_in,
                              void* d_out, int out_size) {
    const float* pred = (const float*)d_in[0];
    float* out = (float*)d_out;
    (void)in_sizes; (void)n_in; (void)out_size;

    void* cnt_addr = nullptr;
    cudaGetSymbolAddress(&cnt_addr, g_cnts);
    cudaMemsetAsync(cnt_addr, 0, (BATCH * NCLS + BATCH) * sizeof(int));

    filter_kernel<<<(BATCH * NANCH + 255) / 256, 256>>>(pred);

    int nms_smem = 4 * CLSCAP * 16 + 4 * CLSCAP * 8 * 4;   // 48 KB
    cudaFuncSetAttribute(nms_kernel, cudaFuncAttributeMaxDynamicSharedMemorySize, nms_smem);
    nms_kernel<<<(BATCH * NCLS + 3) / 4, 128, nms_smem>>>(pred);

    output_kernel<<<BATCH, 1024>>>(pred, out);
}